// round 10
// baseline (speedup 1.0000x reference)
#include <cuda_runtime.h>
#include <math.h>

#define Bc   8
#define Vc   8
#define Nc   1000
#define Dc   256
#define Hc   8
#define KSc  32
#define BVc  64

#define NEG_INF __int_as_float(0xff800000)

// ---------------- scratch (no allocations allowed) ----------------
__device__ float g_M[768 * 8];          // fused feature matrix (7 feat + 1 flag coeff per row)
__device__ float g_q[BVc * Dc];         // query[b,v,d]
__device__ float g_compat[Hc * BVc * Nc];   // compat[h,b,v,n]  (2 MB)
__device__ float g_ms2[Hc * BVc * 2];   // per (h,b,v): {rowmax, sumexp_local}
__device__ float g_heads[BVc * Dc];     // concated heads [b,v, h*32+k]
__device__ float g_fq[BVc * Dc];        // final_Q
__device__ float g_wl[BVc * 8];         // per (b,v): M_L^T @ fq   (8-vector)
__device__ float g_logits[BVc * Nc];
__device__ float g_ent[Bc];
__device__ unsigned char g_mask[BVc * Nc];

// ---------------------------------------------------------------------------
// k_pre:
//   blocks   0..95  : M = pns1 + pns2[:, :768] @ pns1  (+ flag col)
//   blocks  96..159 : query[b,v] = fixed_context[b] + pcs @ [prev;veh]
//   blocks 160..223 : decode feasibility mask (auto-detect bool/int32/float32)
// ---------------------------------------------------------------------------
__global__ __launch_bounds__(256) void k_pre(
    const float* __restrict__ pns1,   // (768,7)
    const float* __restrict__ pns2,   // (768,769)
    const float* __restrict__ prev,   // (B,V,256)
    const float* __restrict__ veh,    // (B,V,8)
    const float* __restrict__ fc,     // (B,1,256)
    const float* __restrict__ pcs,    // (256,264)
    const void*  __restrict__ maskraw)
{
    int blk = blockIdx.x;
    int tid = threadIdx.x;
    int warp = tid >> 5, lane = tid & 31;

    if (blk < 96) {
        int r = blk * 8 + warp;            // row 0..767
        const float* p2row = pns2 + r * 769;
        float acc[7] = {0.f,0.f,0.f,0.f,0.f,0.f,0.f};
        for (int j = lane; j < 768; j += 32) {
            float p2 = p2row[j];
            const float* p1row = pns1 + j * 7;
            #pragma unroll
            for (int f = 0; f < 7; f++) acc[f] += p2 * p1row[f];
        }
        #pragma unroll
        for (int f = 0; f < 7; f++) {
            #pragma unroll
            for (int o = 16; o > 0; o >>= 1)
                acc[f] += __shfl_down_sync(0xffffffffu, acc[f], o);
        }
        if (lane == 0) {
            #pragma unroll
            for (int f = 0; f < 7; f++) g_M[r * 8 + f] = pns1[r * 7 + f] + acc[f];
            g_M[r * 8 + 7] = p2row[768];   // flag weight
        }
    } else if (blk < 160) {
        int bv = blk - 96;                 // 0..63
        int b = bv >> 3;
        __shared__ float cvs[264];
        for (int j = tid; j < 264; j += 256)
            cvs[j] = (j < 256) ? prev[bv * 256 + j] : veh[bv * 8 + (j - 256)];
        __syncthreads();
        // warp-major matvec: warp handles d = warp, warp+8, ...; lanes stride cols
        for (int d = warp; d < 256; d += 8) {
            const float* wrow = pcs + d * 264;
            float acc = 0.f;
            for (int j = lane; j < 264; j += 32) acc += wrow[j] * cvs[j];
            #pragma unroll
            for (int o = 16; o > 0; o >>= 1) acc += __shfl_down_sync(0xffffffffu, acc, o);
            if (lane == 0) g_q[bv * 256 + d] = fc[b * 256 + d] + acc;
        }
    } else {
        // ---- mask decode with dtype auto-detection ----
        int bv = blk - 160;                // 0..63
        const unsigned int* w = (const unsigned int*)maskraw;
        bool all01 = true, bytes01 = true;
        #pragma unroll 8
        for (int i = 0; i < 64; i++) {
            unsigned int u = w[i];
            if (u > 1u) all01 = false;
            if (((u       ) & 0xffu) > 1u || ((u >>  8) & 0xffu) > 1u ||
                ((u >> 16) & 0xffu) > 1u || ((u >> 24) & 0xffu) > 1u)
                bytes01 = false;
        }
        int mode = all01 ? 1 : (bytes01 ? 0 : 2);
        for (int n = tid; n < Nc; n += 256) {
            int i = bv * Nc + n;
            unsigned char m;
            if (mode == 0)      m = ((const unsigned char*)maskraw)[i] ? 1 : 0;
            else if (mode == 1) m = ((const unsigned int*)maskraw)[i]  ? 1 : 0;
            else                m = (((const float*)maskraw)[i] != 0.0f) ? 1 : 0;
            g_mask[i] = m;
        }
    }
}

// ---------------------------------------------------------------------------
// k_compat: one block per (h,b,v) = 512 blocks, 256 threads (8 warps).
// compat[n] = (dot32(q, gK_s[n]) + dot8(wk, ndf8[n])) / sqrt(32)  (masked),
// stored to smem+global; then block-reduce rowmax and local sumexp -> g_ms2.
// ---------------------------------------------------------------------------
__global__ __launch_bounds__(256) void k_compat(
    const float* __restrict__ ndf,   // (B,V,N,8)
    const float* __restrict__ gKs)   // (H,B,1,N,32)
{
    __shared__ float s_c[Nc];
    __shared__ float s_red[256];
    __shared__ float s_wk[8];

    int hbv = blockIdx.x;
    int h = hbv >> 6, bv = hbv & 63;
    int b = bv >> 3;
    int tid = threadIdx.x, warp = tid >> 5, lane = tid & 31;

    float qv = g_q[bv * 256 + h * 32 + lane];

    // wk = M_K^T q  (one-time, warp 0). Butterfly reductions: ALL 32 lanes
    // participate in every shfl; lane 0 then writes with compile-time indices.
    if (warp == 0) {
        const float* mrow = g_M + (256 + h * 32 + lane) * 8;
        float p[8];
        #pragma unroll
        for (int f = 0; f < 8; f++) p[f] = qv * mrow[f];
        #pragma unroll
        for (int f = 0; f < 8; f++) {
            #pragma unroll
            for (int o = 16; o > 0; o >>= 1)
                p[f] += __shfl_xor_sync(0xffffffffu, p[f], o);
        }
        if (lane == 0) {
            #pragma unroll
            for (int f = 0; f < 8; f++) s_wk[f] = p[f];
        }
    }
    __syncthreads();
    float wk[8];
    #pragma unroll
    for (int f = 0; f < 8; f++) wk[f] = s_wk[f];

    const float inv_sqrt_ks = 0.17677669529663688f;   // 1/sqrt(32)
    const float4* fbase = (const float4*)(ndf + bv * Nc * 8);
    const float* gk = gKs + (h * Bc + b) * Nc * 32;
    const unsigned char* mrow = g_mask + bv * Nc;
    float* gcomp = g_compat + hbv * Nc;

    for (int n = warp; n < Nc; n += 8) {
        float4 f0 = fbase[n * 2];
        float4 f1 = fbase[n * 2 + 1];
        float p = qv * gk[n * 32 + lane];
        #pragma unroll
        for (int o = 16; o > 0; o >>= 1) p += __shfl_down_sync(0xffffffffu, p, o);
        if (lane == 0) {
            p += wk[0]*f0.x + wk[1]*f0.y + wk[2]*f0.z + wk[3]*f0.w
               + wk[4]*f1.x + wk[5]*f1.y + wk[6]*f1.z + wk[7]*f1.w;
            float c = p * inv_sqrt_ks;
            if (!mrow[n]) c = NEG_INF;
            s_c[n] = c;
            gcomp[n] = c;
        }
    }
    __syncthreads();

    // row max
    float m = NEG_INF;
    for (int i = tid; i < Nc; i += 256) m = fmaxf(m, s_c[i]);
    s_red[tid] = m;
    __syncthreads();
    for (int s = 128; s > 0; s >>= 1) {
        if (tid < s) s_red[tid] = fmaxf(s_red[tid], s_red[tid + s]);
        __syncthreads();
    }
    m = s_red[0];
    __syncthreads();

    // local sumexp
    float ss = 0.f;
    for (int i = tid; i < Nc; i += 256) ss += expf(s_c[i] - m);
    s_red[tid] = ss;
    __syncthreads();
    for (int s = 128; s > 0; s >>= 1) {
        if (tid < s) s_red[tid] += s_red[tid + s];
        __syncthreads();
    }
    if (tid == 0) { g_ms2[hbv * 2] = m; g_ms2[hbv * 2 + 1] = s_red[0]; }
}

// ---------------------------------------------------------------------------
// k_heads: one block per (h,b,v) = 512 blocks, 256 threads.
// Combines the 8 per-v (max,sum) into the joint (h,b) softmax normalizer,
// then heads[h,b,v,k] = sum_n attn*gV_s[n,k] + M_V[k]·(sum_n attn*ndf8[n]).
// ---------------------------------------------------------------------------
__global__ __launch_bounds__(256) void k_heads(
    const float* __restrict__ ndf,   // (B,V,N,8)
    const float* __restrict__ gVs)   // (H,B,1,N,32)
{
    __shared__ float s_c[Nc];
    __shared__ float s_MS[2];
    __shared__ float s_acc[8 * 32];
    __shared__ float s_sf[8 * 8];

    int hbv = blockIdx.x;
    int h = hbv >> 6, bv = hbv & 63;
    int b = bv >> 3;
    int tid = threadIdx.x, warp = tid >> 5, lane = tid & 31;

    // joint (h,b) normalizer from 8 per-v partials (warp 0, all lanes in shfls)
    if (warp == 0) {
        float m = NEG_INF, s = 0.f;
        if (lane < 8) {
            int idx = (h * 64 + b * 8 + lane) * 2;
            m = g_ms2[idx];
            s = g_ms2[idx + 1];
        }
        float M = m;
        #pragma unroll
        for (int o = 4; o > 0; o >>= 1) M = fmaxf(M, __shfl_xor_sync(0xffffffffu, M, o));
        float se = (lane < 8) ? s * expf(m - M) : 0.f;
        #pragma unroll
        for (int o = 4; o > 0; o >>= 1) se += __shfl_xor_sync(0xffffffffu, se, o);
        if (lane == 0) { s_MS[0] = M; s_MS[1] = 1.0f / se; }
    }
    // preload compat row to smem
    const float* gcomp = g_compat + hbv * Nc;
    for (int i = tid; i < Nc; i += 256) s_c[i] = gcomp[i];
    __syncthreads();

    float M = s_MS[0], invS = s_MS[1];

    const float4* fbase = (const float4*)(ndf + bv * Nc * 8);
    const float* gv = gVs + (h * Bc + b) * Nc * 32;

    float acc = 0.f;
    float sf[8] = {0.f,0.f,0.f,0.f,0.f,0.f,0.f,0.f};
    for (int n = warp; n < Nc; n += 8) {
        float w = expf(s_c[n] - M) * invS;      // 0 for masked
        float4 f0 = fbase[n * 2];
        float4 f1 = fbase[n * 2 + 1];
        acc += w * gv[n * 32 + lane];
        sf[0] += w * f0.x; sf[1] += w * f0.y; sf[2] += w * f0.z; sf[3] += w * f0.w;
        sf[4] += w * f1.x; sf[5] += w * f1.y; sf[6] += w * f1.z; sf[7] += w * f1.w;
    }
    s_acc[warp * 32 + lane] = acc;
    if (lane == 0) {
        #pragma unroll
        for (int f = 0; f < 8; f++) s_sf[warp * 8 + f] = sf[f];
    }
    __syncthreads();

    if (warp == 0) {
        float a = 0.f;
        #pragma unroll
        for (int w = 0; w < 8; w++) a += s_acc[w * 32 + lane];
        float sft[8];
        #pragma unroll
        for (int f = 0; f < 8; f++) {
            float t = 0.f;
            #pragma unroll
            for (int w = 0; w < 8; w++) t += s_sf[w * 8 + f];
            sft[f] = t;
        }
        const float* cvrow = g_M + (h * 32 + lane) * 8;   // gV-dyn coeffs
        float dyn = cvrow[0]*sft[0] + cvrow[1]*sft[1] + cvrow[2]*sft[2] + cvrow[3]*sft[3]
                  + cvrow[4]*sft[4] + cvrow[5]*sft[5] + cvrow[6]*sft[6] + cvrow[7]*sft[7];
        g_heads[bv * 256 + h * 32 + lane] = a + dyn;
    }
}

// ---------------------------------------------------------------------------
// k_fq: final_Q[b,v] = po @ heads[b,v]; also wl = M_L^T @ fq (8-vector per bv)
// ---------------------------------------------------------------------------
__global__ __launch_bounds__(256) void k_fq(const float* __restrict__ po)
{
    int bv = blockIdx.x;
    int tid = threadIdx.x, warp = tid >> 5, lane = tid & 31;
    __shared__ float hsm[256];
    __shared__ float fqsm[256];
    hsm[tid] = g_heads[bv * 256 + tid];
    __syncthreads();
    const float* wrow = po + tid * 256;
    float acc = 0.f;
    for (int j = 0; j < 256; j++) acc += wrow[j] * hsm[j];
    g_fq[bv * 256 + tid] = acc;
    fqsm[tid] = acc;
    __syncthreads();
    // wl[f] = sum_d fq[d] * M_L[d][f] ; warp w handles f = w
    float a = 0.f;
    for (int d = lane; d < 256; d += 32) a += fqsm[d] * g_M[(512 + d) * 8 + warp];
    #pragma unroll
    for (int o = 16; o > 0; o >>= 1) a += __shfl_down_sync(0xffffffffu, a, o);
    if (lane == 0) g_wl[bv * 8 + warp] = a;
}

// ---------------------------------------------------------------------------
// k_logits: logits[b,v,n] = tanh((dot256(fq, lK_s[n]) + dot8(wl, ndf8))/16)*10,
// masked. grid (64 bv, 8 tiles of 125 n), 256 thr, warp-per-n, float4 loads.
// ---------------------------------------------------------------------------
__global__ __launch_bounds__(256) void k_logits(
    const float* __restrict__ ndf,             // (B,V,N,8)
    const float* __restrict__ lKs)             // (B,1,N,256)
{
    int bv = blockIdx.x;
    int b = bv >> 3;
    int tile = blockIdx.y;                     // 0..7
    int tid = threadIdx.x, warp = tid >> 5, lane = tid & 31;

    __shared__ float fqsm[256];
    __shared__ float wlsm[8];
    fqsm[tid] = g_fq[bv * 256 + tid];
    if (tid < 8) wlsm[tid] = g_wl[bv * 8 + tid];
    __syncthreads();

    float4 fqa = ((const float4*)fqsm)[lane];          // d = lane*4 .. +3
    float4 fqb = ((const float4*)fqsm)[lane + 32];     // d = 128 + lane*4 ..
    float wl[8];
    #pragma unroll
    for (int f = 0; f < 8; f++) wl[f] = wlsm[f];

    const float4* fbase = (const float4*)(ndf + bv * Nc * 8);
    const float* lk = lKs + b * Nc * 256;
    const unsigned char* mrow = g_mask + bv * Nc;

    int n0 = tile * 125;
    for (int n = n0 + warp; n < n0 + 125; n += 8) {
        const float4* lkr = (const float4*)(lk + n * 256);
        float4 v0 = lkr[lane];
        float4 v1 = lkr[lane + 32];
        float4 f0 = fbase[n * 2];
        float4 f1 = fbase[n * 2 + 1];
        float p = fqa.x*v0.x + fqa.y*v0.y + fqa.z*v0.z + fqa.w*v0.w
                + fqb.x*v1.x + fqb.y*v1.y + fqb.z*v1.z + fqb.w*v1.w;
        #pragma unroll
        for (int o = 16; o > 0; o >>= 1) p += __shfl_down_sync(0xffffffffu, p, o);
        if (lane == 0) {
            p += wl[0]*f0.x + wl[1]*f0.y + wl[2]*f0.z + wl[3]*f0.w
               + wl[4]*f1.x + wl[5]*f1.y + wl[6]*f1.z + wl[7]*f1.w;
            float lg = tanhf(p * 0.0625f) * 10.0f;
            if (!mrow[n]) lg = NEG_INF;
            g_logits[bv * Nc + n] = lg;
        }
    }
}

// ---------------------------------------------------------------------------
// k_select: one block per b. softmax over v*n=8000, argmax (first-index tie),
// writes vec/node/logprob + per-b entropy term to g_ent.
// ---------------------------------------------------------------------------
__global__ __launch_bounds__(1024) void k_select(float* __restrict__ out)
{
    __shared__ float s_v[1024];
    __shared__ int   s_i[1024];
    int b = blockIdx.x;
    int tid = threadIdx.x;
    const float* lg = g_logits + b * 8000;

    float bm = NEG_INF; int bi = 0x7fffffff;
    for (int i = tid; i < 8000; i += 1024) {
        float x = lg[i];
        if (x > bm || (x == bm && i < bi)) { bm = x; bi = i; }
    }
    s_v[tid] = bm; s_i[tid] = bi;
    __syncthreads();
    for (int s = 512; s > 0; s >>= 1) {
        if (tid < s) {
            float xv = s_v[tid + s]; int xi = s_i[tid + s];
            if (xv > s_v[tid] || (xv == s_v[tid] && xi < s_i[tid])) {
                s_v[tid] = xv; s_i[tid] = xi;
            }
        }
        __syncthreads();
    }
    float m = s_v[0];
    int op = s_i[0];
    __syncthreads();

    float ssum = 0.f;
    for (int i = tid; i < 8000; i += 1024) ssum += expf(lg[i] - m);
    s_v[tid] = ssum;
    __syncthreads();
    for (int s = 512; s > 0; s >>= 1) {
        if (tid < s) s_v[tid] += s_v[tid + s];
        __syncthreads();
    }
    if (tid == 0) {
        float total = s_v[0];
        float prob    = 1.0f / total;
        float logprob = -logf(total);
        out[b]      = (float)(op / Nc);
        out[8 + b]  = (float)(op % Nc);
        out[16 + b] = logprob;
        g_ent[b]    = prob * logprob;
    }
}

// k_ent: entropy = -sum_b prob*logprob
__global__ void k_ent(float* __restrict__ out)
{
    int lane = threadIdx.x;
    float e = (lane < 8) ? g_ent[lane] : 0.f;
    #pragma unroll
    for (int o = 4; o > 0; o >>= 1) e += __shfl_xor_sync(0xffffffffu, e, o);
    if (lane == 0) out[24] = -e;
}

// ---------------------------------------------------------------------------
extern "C" void kernel_launch(void* const* d_in, const int* in_sizes, int n_in,
                              void* d_out, int out_size)
{
    const float* fc   = (const float*)d_in[1];   // fixed_context
    const float* prev = (const float*)d_in[2];   // prev_node_embeddings
    const float* ndf  = (const float*)d_in[3];   // node_dynamic_features
    const float* veh  = (const float*)d_in[4];   // vehicle_dynamic_features
    const float* gVs  = (const float*)d_in[5];   // glimpse_V_static
    const float* gKs  = (const float*)d_in[6];   // glimpse_K_static
    const float* lKs  = (const float*)d_in[7];   // logit_K_static
    const void*  mask = (const void*)d_in[8];    // feasibility_mask (dtype auto-detected)
    const float* pcs  = (const float*)d_in[9];
    const float* pns1 = (const float*)d_in[10];
    const float* pns2 = (const float*)d_in[11];
    const float* po   = (const float*)d_in[12];
    float* out = (float*)d_out;

    k_pre<<<224, 256>>>(pns1, pns2, prev, veh, fc, pcs, mask);
    k_compat<<<512, 256>>>(ndf, gKs);
    k_heads<<<512, 256>>>(ndf, gVs);
    k_fq<<<64, 256>>>(po);
    dim3 gl(64, 8);
    k_logits<<<gl, 256>>>(ndf, lKs);
    k_select<<<8, 1024>>>(out);
    k_ent<<<1, 32>>>(out);
}

// round 12
// speedup vs baseline: 3.3561x; 3.3561x over previous
#include <cuda_runtime.h>
#include <math.h>

#define Bc   8
#define Vc   8
#define Nc   1000
#define Dc   256
#define Hc   8
#define KSc  32
#define BVc  64

#define NEG_INF __int_as_float(0xff800000)

// ---------------- scratch (no allocations allowed) ----------------
__device__ float g_M[768 * 8];          // fused feature matrix (7 feat + 1 flag coeff per row)
__device__ float g_q[BVc * Dc];         // query[b,v,d]
__device__ float g_compat[Hc * BVc * Nc];   // compat[h,b,v,n]  (2 MB)
__device__ float g_ms2[Hc * BVc * 2];   // per (h,b,v): {rowmax, sumexp_local}
__device__ float g_heads[BVc * Dc];     // concated heads [b,v, h*32+k]
__device__ float g_fq[BVc * Dc];        // final_Q
__device__ float g_wl[BVc * 8];         // per (b,v): M_L^T @ fq   (8-vector)
__device__ float g_logits[BVc * Nc];
__device__ unsigned char g_mask[BVc * Nc];

// ---------------------------------------------------------------------------
// k_pre:
//   blocks   0..95  : M = pns1 + pns2[:, :768] @ pns1  (+ flag col)
//   blocks  96..159 : query[b,v] = fixed_context[b] + pcs @ [prev;veh]
//   blocks 160..223 : decode feasibility mask (auto-detect bool/int32/float32)
// ---------------------------------------------------------------------------
__global__ __launch_bounds__(256) void k_pre(
    const float* __restrict__ pns1,   // (768,7)
    const float* __restrict__ pns2,   // (768,769)
    const float* __restrict__ prev,   // (B,V,256)
    const float* __restrict__ veh,    // (B,V,8)
    const float* __restrict__ fc,     // (B,1,256)
    const float* __restrict__ pcs,    // (256,264)
    const void*  __restrict__ maskraw)
{
    int blk = blockIdx.x;
    int tid = threadIdx.x;
    int warp = tid >> 5, lane = tid & 31;

    if (blk < 96) {
        int r = blk * 8 + warp;            // row 0..767
        const float* p2row = pns2 + r * 769;
        float acc[7] = {0.f,0.f,0.f,0.f,0.f,0.f,0.f};
        for (int j = lane; j < 768; j += 32) {
            float p2 = p2row[j];
            const float* p1row = pns1 + j * 7;
            #pragma unroll
            for (int f = 0; f < 7; f++) acc[f] += p2 * p1row[f];
        }
        #pragma unroll
        for (int f = 0; f < 7; f++) {
            #pragma unroll
            for (int o = 16; o > 0; o >>= 1)
                acc[f] += __shfl_xor_sync(0xffffffffu, acc[f], o);
        }
        if (lane == 0) {
            #pragma unroll
            for (int f = 0; f < 7; f++) g_M[r * 8 + f] = pns1[r * 7 + f] + acc[f];
            g_M[r * 8 + 7] = p2row[768];   // flag weight
        }
    } else if (blk < 160) {
        int bv = blk - 96;                 // 0..63
        int b = bv >> 3;
        __shared__ __align__(16) float cvs[264];
        for (int j = tid; j < 264; j += 256)
            cvs[j] = (j < 256) ? prev[bv * 256 + j] : veh[bv * 8 + (j - 256)];
        __syncthreads();
        for (int d = warp; d < 256; d += 8) {
            const float* wrow = pcs + d * 264;
            float acc = 0.f;
            for (int j = lane; j < 264; j += 32) acc += wrow[j] * cvs[j];
            #pragma unroll
            for (int o = 16; o > 0; o >>= 1) acc += __shfl_xor_sync(0xffffffffu, acc, o);
            if (lane == 0) g_q[bv * 256 + d] = fc[b * 256 + d] + acc;
        }
    } else {
        // ---- mask decode with dtype auto-detection ----
        int bv = blk - 160;                // 0..63
        const unsigned int* w = (const unsigned int*)maskraw;
        bool all01 = true, bytes01 = true;
        #pragma unroll 8
        for (int i = 0; i < 64; i++) {
            unsigned int u = w[i];
            if (u > 1u) all01 = false;
            if (((u       ) & 0xffu) > 1u || ((u >>  8) & 0xffu) > 1u ||
                ((u >> 16) & 0xffu) > 1u || ((u >> 24) & 0xffu) > 1u)
                bytes01 = false;
        }
        int mode = all01 ? 1 : (bytes01 ? 0 : 2);
        for (int n = tid; n < Nc; n += 256) {
            int i = bv * Nc + n;
            unsigned char m;
            if (mode == 0)      m = ((const unsigned char*)maskraw)[i] ? 1 : 0;
            else if (mode == 1) m = ((const unsigned int*)maskraw)[i]  ? 1 : 0;
            else                m = (((const float*)maskraw)[i] != 0.0f) ? 1 : 0;
            g_mask[i] = m;
        }
    }
}

// ---------------------------------------------------------------------------
// k_compat: one block per (h,b,v) = 512 blocks, 256 threads (8 warps).
// QUAD layout: 4 lanes per n (each covers 8 of the 32 k's via 2 float4 loads),
// depth-2 shfl_xor closes the dot. 8 n per warp-iteration, 16 iterations.
// compat[n] -> smem + global; block-reduce rowmax + local sumexp -> g_ms2.
// ---------------------------------------------------------------------------
__global__ __launch_bounds__(256) void k_compat(
    const float* __restrict__ ndf,   // (B,V,N,8)
    const float* __restrict__ gKs)   // (H,B,1,N,32)
{
    __shared__ __align__(16) float s_c[Nc];
    __shared__ __align__(16) float s_red[256];
    __shared__ __align__(16) float s_wk[8];
    __shared__ __align__(16) float qsm[32];

    int hbv = blockIdx.x;
    int h = hbv >> 6, bv = hbv & 63;
    int b = bv >> 3;
    int tid = threadIdx.x, warp = tid >> 5, lane = tid & 31;

    // warp 0: stash q slice, compute wk = M_K^T q (butterfly, all lanes in shfl)
    if (warp == 0) {
        float qv = g_q[bv * 256 + h * 32 + lane];
        qsm[lane] = qv;
        const float* mr = g_M + (256 + h * 32 + lane) * 8;
        float p[8];
        #pragma unroll
        for (int f = 0; f < 8; f++) p[f] = qv * mr[f];
        #pragma unroll
        for (int f = 0; f < 8; f++) {
            #pragma unroll
            for (int o = 16; o > 0; o >>= 1)
                p[f] += __shfl_xor_sync(0xffffffffu, p[f], o);
        }
        if (lane == 0) {
            #pragma unroll
            for (int f = 0; f < 8; f++) s_wk[f] = p[f];
        }
    }
    __syncthreads();

    float wk[8];
    #pragma unroll
    for (int f = 0; f < 8; f++) wk[f] = s_wk[f];

    int q = lane & 3;
    float4 qa = ((const float4*)qsm)[q * 2];
    float4 qb = ((const float4*)qsm)[q * 2 + 1];

    const float inv_sqrt_ks = 0.17677669529663688f;   // 1/sqrt(32)
    const float4* fbase = (const float4*)(ndf + bv * Nc * 8);
    const float* gk = gKs + (h * Bc + b) * Nc * 32;
    const unsigned char* mrow = g_mask + bv * Nc;
    float* gcomp = g_compat + hbv * Nc;

    #pragma unroll 4
    for (int it = 0; it < 16; it++) {
        int n = it * 64 + warp * 8 + (lane >> 2);
        int nl = (n < Nc) ? n : (Nc - 1);
        const float* gr = gk + nl * 32 + q * 8;
        float4 ga = *(const float4*)gr;
        float4 gb = *(const float4*)(gr + 4);
        float p = qa.x*ga.x + qa.y*ga.y + qa.z*ga.z + qa.w*ga.w
                + qb.x*gb.x + qb.y*gb.y + qb.z*gb.z + qb.w*gb.w;
        p += __shfl_xor_sync(0xffffffffu, p, 1);
        p += __shfl_xor_sync(0xffffffffu, p, 2);
        float4 f0 = fbase[nl * 2];
        float4 f1 = fbase[nl * 2 + 1];
        p += wk[0]*f0.x + wk[1]*f0.y + wk[2]*f0.z + wk[3]*f0.w
           + wk[4]*f1.x + wk[5]*f1.y + wk[6]*f1.z + wk[7]*f1.w;
        float c = p * inv_sqrt_ks;
        if (!mrow[nl]) c = NEG_INF;
        if (q == 0 && n < Nc) { s_c[n] = c; gcomp[n] = c; }
    }
    __syncthreads();

    // row max
    float m = NEG_INF;
    for (int i = tid; i < Nc; i += 256) m = fmaxf(m, s_c[i]);
    s_red[tid] = m;
    __syncthreads();
    for (int s = 128; s > 0; s >>= 1) {
        if (tid < s) s_red[tid] = fmaxf(s_red[tid], s_red[tid + s]);
        __syncthreads();
    }
    m = s_red[0];
    __syncthreads();

    // local sumexp
    float ss = 0.f;
    for (int i = tid; i < Nc; i += 256) ss += expf(s_c[i] - m);
    s_red[tid] = ss;
    __syncthreads();
    for (int s = 128; s > 0; s >>= 1) {
        if (tid < s) s_red[tid] += s_red[tid + s];
        __syncthreads();
    }
    if (tid == 0) { g_ms2[hbv * 2] = m; g_ms2[hbv * 2 + 1] = s_red[0]; }
}

// ---------------------------------------------------------------------------
// k_heads: one block per (h,b,v) = 512 blocks, 256 threads. QUAD layout.
// Joint (h,b) normalizer from 8 per-v partials, then
// heads[h,b,v,k] = sum_n attn*gV_s[n,k] + M_V[k]·(sum_n attn*ndf8[n]).
// ---------------------------------------------------------------------------
__global__ __launch_bounds__(256) void k_heads(
    const float* __restrict__ ndf,   // (B,V,N,8)
    const float* __restrict__ gVs)   // (H,B,1,N,32)
{
    __shared__ __align__(16) float s_c[Nc];
    __shared__ __align__(16) float s_acc[8 * 32];
    __shared__ __align__(16) float s_sf[8 * 8];
    __shared__ __align__(16) float s_MS[4];

    int hbv = blockIdx.x;
    int h = hbv >> 6, bv = hbv & 63;
    int b = bv >> 3;
    int tid = threadIdx.x, warp = tid >> 5, lane = tid & 31;

    // joint (h,b) normalizer (warp 0; all 32 lanes participate in shfls)
    if (warp == 0) {
        float m = NEG_INF, s = 0.f;
        if (lane < 8) {
            int idx = (h * 64 + b * 8 + lane) * 2;
            m = g_ms2[idx];
            s = g_ms2[idx + 1];
        }
        float M = m;
        #pragma unroll
        for (int o = 4; o > 0; o >>= 1) M = fmaxf(M, __shfl_xor_sync(0xffffffffu, M, o));
        float se = (lane < 8) ? s * expf(m - M) : 0.f;
        #pragma unroll
        for (int o = 4; o > 0; o >>= 1) se += __shfl_xor_sync(0xffffffffu, se, o);
        if (lane == 0) { s_MS[0] = M; s_MS[1] = 1.0f / se; }
    }
    const float* gcomp = g_compat + hbv * Nc;
    for (int i = tid; i < Nc; i += 256) s_c[i] = gcomp[i];
    __syncthreads();

    float M = s_MS[0], invS = s_MS[1];

    const float4* fbase = (const float4*)(ndf + bv * Nc * 8);
    const float* gv = gVs + (h * Bc + b) * Nc * 32;

    int q = lane & 3;
    float4 aca = make_float4(0.f,0.f,0.f,0.f);
    float4 acb = make_float4(0.f,0.f,0.f,0.f);
    float sf[8] = {0.f,0.f,0.f,0.f,0.f,0.f,0.f,0.f};

    #pragma unroll 4
    for (int it = 0; it < 16; it++) {
        int n = it * 64 + warp * 8 + (lane >> 2);
        int nl = (n < Nc) ? n : (Nc - 1);
        float w = (n < Nc) ? expf(s_c[nl] - M) * invS : 0.f;
        const float* gr = gv + nl * 32 + q * 8;
        float4 ga = *(const float4*)gr;
        float4 gb = *(const float4*)(gr + 4);
        aca.x += w * ga.x; aca.y += w * ga.y; aca.z += w * ga.z; aca.w += w * ga.w;
        acb.x += w * gb.x; acb.y += w * gb.y; acb.z += w * gb.z; acb.w += w * gb.w;
        float4 f0 = fbase[nl * 2];
        float4 f1 = fbase[nl * 2 + 1];
        sf[0] += w * f0.x; sf[1] += w * f0.y; sf[2] += w * f0.z; sf[3] += w * f0.w;
        sf[4] += w * f1.x; sf[5] += w * f1.y; sf[6] += w * f1.z; sf[7] += w * f1.w;
    }
    // reduce across quad-columns (lanes sharing q): offsets 4, 8, 16
    #pragma unroll
    for (int o = 4; o <= 16; o <<= 1) {
        aca.x += __shfl_xor_sync(0xffffffffu, aca.x, o);
        aca.y += __shfl_xor_sync(0xffffffffu, aca.y, o);
        aca.z += __shfl_xor_sync(0xffffffffu, aca.z, o);
        aca.w += __shfl_xor_sync(0xffffffffu, aca.w, o);
        acb.x += __shfl_xor_sync(0xffffffffu, acb.x, o);
        acb.y += __shfl_xor_sync(0xffffffffu, acb.y, o);
        acb.z += __shfl_xor_sync(0xffffffffu, acb.z, o);
        acb.w += __shfl_xor_sync(0xffffffffu, acb.w, o);
        #pragma unroll
        for (int f = 0; f < 8; f++) sf[f] += __shfl_xor_sync(0xffffffffu, sf[f], o);
    }
    if (lane < 4) {
        ((float4*)(s_acc + warp * 32 + lane * 8))[0] = aca;
        ((float4*)(s_acc + warp * 32 + lane * 8))[1] = acb;
    }
    if (lane == 0) {
        #pragma unroll
        for (int f = 0; f < 8; f++) s_sf[warp * 8 + f] = sf[f];
    }
    __syncthreads();

    if (warp == 0) {
        float a = 0.f;
        #pragma unroll
        for (int w = 0; w < 8; w++) a += s_acc[w * 32 + lane];
        float sft[8];
        #pragma unroll
        for (int f = 0; f < 8; f++) {
            float t = 0.f;
            #pragma unroll
            for (int w = 0; w < 8; w++) t += s_sf[w * 8 + f];
            sft[f] = t;
        }
        const float* cvrow = g_M + (h * 32 + lane) * 8;   // gV-dyn coeffs
        float dyn = cvrow[0]*sft[0] + cvrow[1]*sft[1] + cvrow[2]*sft[2] + cvrow[3]*sft[3]
                  + cvrow[4]*sft[4] + cvrow[5]*sft[5] + cvrow[6]*sft[6] + cvrow[7]*sft[7];
        g_heads[bv * 256 + h * 32 + lane] = a + dyn;
    }
}

// ---------------------------------------------------------------------------
// k_fq: final_Q[b,v] = po @ heads[b,v] (COALESCED: lane covers its 8-float
// slice of the po row via 2x LDG.128), also wl = M_L^T @ fq.
// ---------------------------------------------------------------------------
__global__ __launch_bounds__(256) void k_fq(const float* __restrict__ po)
{
    int bv = blockIdx.x;
    int tid = threadIdx.x, warp = tid >> 5, lane = tid & 31;
    __shared__ __align__(16) float hsm[256];
    __shared__ __align__(16) float fqsm[256];
    hsm[tid] = g_heads[bv * 256 + tid];
    __syncthreads();

    float4 ha = ((const float4*)hsm)[lane * 2];
    float4 hb = ((const float4*)hsm)[lane * 2 + 1];

    for (int d = warp; d < 256; d += 8) {
        const float* pr = po + d * 256 + lane * 8;
        float4 pa = *(const float4*)pr;
        float4 pb = *(const float4*)(pr + 4);
        float p = ha.x*pa.x + ha.y*pa.y + ha.z*pa.z + ha.w*pa.w
                + hb.x*pb.x + hb.y*pb.y + hb.z*pb.z + hb.w*pb.w;
        #pragma unroll
        for (int o = 16; o > 0; o >>= 1) p += __shfl_xor_sync(0xffffffffu, p, o);
        if (lane == 0) { g_fq[bv * 256 + d] = p; fqsm[d] = p; }
    }
    __syncthreads();

    // wl[f] = sum_d fq[d] * M_L[d][f] ; warp w handles f = w
    float a = 0.f;
    for (int d = lane; d < 256; d += 32) a += fqsm[d] * g_M[(512 + d) * 8 + warp];
    #pragma unroll
    for (int o = 16; o > 0; o >>= 1) a += __shfl_xor_sync(0xffffffffu, a, o);
    if (lane == 0) g_wl[bv * 8 + warp] = a;
}

// ---------------------------------------------------------------------------
// k_logits: logits[b,v,n] = tanh((dot256(fq, lK_s[n]) + dot8(wl, ndf8))/16)*10,
// masked. grid (64 bv, 8 tiles of 125 n), 256 thr, warp-per-n, float4 loads.
// ---------------------------------------------------------------------------
__global__ __launch_bounds__(256) void k_logits(
    const float* __restrict__ ndf,             // (B,V,N,8)
    const float* __restrict__ lKs)             // (B,1,N,256)
{
    int bv = blockIdx.x;
    int b = bv >> 3;
    int tile = blockIdx.y;                     // 0..7
    int tid = threadIdx.x, warp = tid >> 5, lane = tid & 31;

    __shared__ __align__(16) float fqsm[256];
    __shared__ __align__(16) float wlsm[8];
    fqsm[tid] = g_fq[bv * 256 + tid];
    if (tid < 8) wlsm[tid] = g_wl[bv * 8 + tid];
    __syncthreads();

    float4 fqa = ((const float4*)fqsm)[lane * 2];
    float4 fqb = ((const float4*)fqsm)[lane * 2 + 1];
    float wl[8];
    #pragma unroll
    for (int f = 0; f < 8; f++) wl[f] = wlsm[f];

    const float4* fbase = (const float4*)(ndf + bv * Nc * 8);
    const float* lk = lKs + b * Nc * 256;
    const unsigned char* mrow = g_mask + bv * Nc;

    int n0 = tile * 125;
    for (int n = n0 + warp; n < n0 + 125; n += 8) {
        const float* lkr = lk + n * 256 + lane * 8;
        float4 v0 = *(const float4*)lkr;
        float4 v1 = *(const float4*)(lkr + 4);
        float4 f0 = fbase[n * 2];
        float4 f1 = fbase[n * 2 + 1];
        float p = fqa.x*v0.x + fqa.y*v0.y + fqa.z*v0.z + fqa.w*v0.w
                + fqb.x*v1.x + fqb.y*v1.y + fqb.z*v1.z + fqb.w*v1.w;
        #pragma unroll
        for (int o = 16; o > 0; o >>= 1) p += __shfl_xor_sync(0xffffffffu, p, o);
        if (lane == 0) {
            p += wl[0]*f0.x + wl[1]*f0.y + wl[2]*f0.z + wl[3]*f0.w
               + wl[4]*f1.x + wl[5]*f1.y + wl[6]*f1.z + wl[7]*f1.w;
            float lg = tanhf(p * 0.0625f) * 10.0f;
            if (!mrow[n]) lg = NEG_INF;
            g_logits[bv * Nc + n] = lg;
        }
    }
}

// ---------------------------------------------------------------------------
// k_sel: ONE block, 1024 threads = 8 groups of 128 (one per batch b).
// Per-b: argmax (first-index tie-break) + sumexp -> vec/node/logprob;
// then in-block entropy combine. Writes all 25 outputs.
// ---------------------------------------------------------------------------
__global__ __launch_bounds__(1024) void k_sel(float* __restrict__ out)
{
    __shared__ __align__(16) float s_v[32];
    __shared__ __align__(16) int   s_i[32];
    __shared__ __align__(16) float s_m[8];
    __shared__ __align__(16) float s_s[32];
    __shared__ __align__(16) float s_e[8];

    int tid = threadIdx.x;
    int g = tid >> 7, t = tid & 127;           // group = batch, 4 warps per group
    int wig = t >> 5, lane = tid & 31;
    const float* lg = g_logits + g * 8000;

    // local argmax (ascending stride keeps first occurrence)
    float bm = NEG_INF; int bi = 0x7fffffff;
    for (int i = t; i < 8000; i += 128) {
        float x = lg[i];
        if (x > bm) { bm = x; bi = i; }
    }
    // warp reduce (val, idx), smaller idx wins ties
    #pragma unroll
    for (int o = 16; o > 0; o >>= 1) {
        float xv = __shfl_down_sync(0xffffffffu, bm, o);
        int   xi = __shfl_down_sync(0xffffffffu, bi, o);
        if (xv > bm || (xv == bm && xi < bi)) { bm = xv; bi = xi; }
    }
    if (lane == 0) { s_v[g * 4 + wig] = bm; s_i[g * 4 + wig] = bi; }
    __syncthreads();

    int op = 0;
    if (t == 0) {
        float m = s_v[g * 4]; op = s_i[g * 4];
        #pragma unroll
        for (int w = 1; w < 4; w++) {
            float xv = s_v[g * 4 + w]; int xi = s_i[g * 4 + w];
            if (xv > m || (xv == m && xi < op)) { m = xv; op = xi; }
        }
        s_m[g] = m;
    }
    __syncthreads();

    float m = s_m[g];
    float ssum = 0.f;
    for (int i = t; i < 8000; i += 128) ssum += expf(lg[i] - m);
    #pragma unroll
    for (int o = 16; o > 0; o >>= 1) ssum += __shfl_xor_sync(0xffffffffu, ssum, o);
    if (lane == 0) s_s[g * 4 + wig] = ssum;
    __syncthreads();

    if (t == 0) {
        float total = s_s[g * 4] + s_s[g * 4 + 1] + s_s[g * 4 + 2] + s_s[g * 4 + 3];
        float prob    = 1.0f / total;
        float logprob = -logf(total);
        out[g]      = (float)(op / Nc);
        out[8 + g]  = (float)(op % Nc);
        out[16 + g] = logprob;
        s_e[g]      = prob * logprob;
    }
    __syncthreads();
    if (tid == 0) {
        float e = 0.f;
        #pragma unroll
        for (int b = 0; b < 8; b++) e += s_e[b];
        out[24] = -e;
    }
}

// ---------------------------------------------------------------------------
extern "C" void kernel_launch(void* const* d_in, const int* in_sizes, int n_in,
                              void* d_out, int out_size)
{
    const float* fc   = (const float*)d_in[1];   // fixed_context
    const float* prev = (const float*)d_in[2];   // prev_node_embeddings
    const float* ndf  = (const float*)d_in[3];   // node_dynamic_features
    const float* veh  = (const float*)d_in[4];   // vehicle_dynamic_features
    const float* gVs  = (const float*)d_in[5];   // glimpse_V_static
    const float* gKs  = (const float*)d_in[6];   // glimpse_K_static
    const float* lKs  = (const float*)d_in[7];   // logit_K_static
    const void*  mask = (const void*)d_in[8];    // feasibility_mask (dtype auto-detected)
    const float* pcs  = (const float*)d_in[9];
    const float* pns1 = (const float*)d_in[10];
    const float* pns2 = (const float*)d_in[11];
    const float* po   = (const float*)d_in[12];
    float* out = (float*)d_out;

    k_pre<<<224, 256>>>(pns1, pns2, prev, veh, fc, pcs, mask);
    k_compat<<<512, 256>>>(ndf, gKs);
    k_heads<<<512, 256>>>(ndf, gVs);
    k_fq<<<64, 256>>>(po);
    dim3 gl(64, 8);
    k_logits<<<gl, 256>>>(ndf, lKs);
    k_sel<<<1, 1024>>>(out);
}

// round 14
// speedup vs baseline: 3.3576x; 1.0004x over previous
#include <cuda_runtime.h>
#include <math.h>

#define Bc   8
#define Vc   8
#define Nc   1000
#define Dc   256
#define Hc   8
#define KSc  32
#define BVc  64

#define NEG_INF __int_as_float(0xff800000)

// ---------------- scratch (no allocations allowed) ----------------
__device__ float g_M[768 * 8];          // fused feature matrix (7 feat + 1 flag coeff per row)
__device__ float g_q[BVc * Dc];         // query[b,v,d]
__device__ float g_poT[Dc * Dc];        // po transposed: g_poT[j*256+d] = po[d*256+j]
__device__ float g_compat[Hc * BVc * Nc];   // compat[h,b,v,n]  (2 MB)
__device__ float g_ms2[Hc * BVc * 2];   // per (h,b,v): {rowmax, sumexp_local}
__device__ float g_heads[BVc * Dc];     // concated heads [b,v, h*32+k]
__device__ float g_fq[BVc * Dc];        // final_Q
__device__ float g_wl[BVc * 8];         // per (b,v): M_L^T @ fq   (8-vector)
__device__ float g_logits[BVc * Nc];
__device__ unsigned char g_mask[BVc * Nc];

// ---------------------------------------------------------------------------
// k_pre:
//   blocks   0..95  : M = pns1 + pns2[:, :768] @ pns1  (+ flag col)
//   blocks  96..159 : query[b,v] = fixed_context[b] + pcs @ [prev;veh]
//   blocks 160..223 : decode feasibility mask (auto-detect bool/int32/float32)
//   blocks 224..287 : transpose po (32x32 smem tiles)
// ---------------------------------------------------------------------------
__global__ __launch_bounds__(256) void k_pre(
    const float* __restrict__ pns1,   // (768,7)
    const float* __restrict__ pns2,   // (768,769)
    const float* __restrict__ prev,   // (B,V,256)
    const float* __restrict__ veh,    // (B,V,8)
    const float* __restrict__ fc,     // (B,1,256)
    const float* __restrict__ pcs,    // (256,264)
    const float* __restrict__ po,     // (256,256)
    const void*  __restrict__ maskraw)
{
    int blk = blockIdx.x;
    int tid = threadIdx.x;
    int warp = tid >> 5, lane = tid & 31;

    if (blk < 96) {
        int r = blk * 8 + warp;            // row 0..767
        const float* p2row = pns2 + r * 769;
        float acc[7] = {0.f,0.f,0.f,0.f,0.f,0.f,0.f};
        for (int j = lane; j < 768; j += 32) {
            float p2 = p2row[j];
            const float* p1row = pns1 + j * 7;
            #pragma unroll
            for (int f = 0; f < 7; f++) acc[f] += p2 * p1row[f];
        }
        #pragma unroll
        for (int f = 0; f < 7; f++) {
            #pragma unroll
            for (int o = 16; o > 0; o >>= 1)
                acc[f] += __shfl_xor_sync(0xffffffffu, acc[f], o);
        }
        if (lane == 0) {
            #pragma unroll
            for (int f = 0; f < 7; f++) g_M[r * 8 + f] = pns1[r * 7 + f] + acc[f];
            g_M[r * 8 + 7] = p2row[768];   // flag weight
        }
    } else if (blk < 160) {
        int bv = blk - 96;                 // 0..63
        int b = bv >> 3;
        __shared__ __align__(16) float cvs[264];
        for (int j = tid; j < 264; j += 256)
            cvs[j] = (j < 256) ? prev[bv * 256 + j] : veh[bv * 8 + (j - 256)];
        __syncthreads();
        for (int d = warp; d < 256; d += 8) {
            const float* wrow = pcs + d * 264;
            float acc = 0.f;
            for (int j = lane; j < 264; j += 32) acc += wrow[j] * cvs[j];
            #pragma unroll
            for (int o = 16; o > 0; o >>= 1) acc += __shfl_xor_sync(0xffffffffu, acc, o);
            if (lane == 0) g_q[bv * 256 + d] = fc[b * 256 + d] + acc;
        }
    } else if (blk < 224) {
        // ---- mask decode with dtype auto-detection ----
        int bv = blk - 160;                // 0..63
        const unsigned int* w = (const unsigned int*)maskraw;
        bool all01 = true, bytes01 = true;
        #pragma unroll 8
        for (int i = 0; i < 64; i++) {
            unsigned int u = w[i];
            if (u > 1u) all01 = false;
            if (((u       ) & 0xffu) > 1u || ((u >>  8) & 0xffu) > 1u ||
                ((u >> 16) & 0xffu) > 1u || ((u >> 24) & 0xffu) > 1u)
                bytes01 = false;
        }
        int mode = all01 ? 1 : (bytes01 ? 0 : 2);
        for (int n = tid; n < Nc; n += 256) {
            int i = bv * Nc + n;
            unsigned char m;
            if (mode == 0)      m = ((const unsigned char*)maskraw)[i] ? 1 : 0;
            else if (mode == 1) m = ((const unsigned int*)maskraw)[i]  ? 1 : 0;
            else                m = (((const float*)maskraw)[i] != 0.0f) ? 1 : 0;
            g_mask[i] = m;
        }
    } else {
        // ---- transpose po into g_poT (32x32 tile, +1 pad = conflict-free) ----
        int t = blk - 224;                 // 0..63
        int tr = (t >> 3) * 32;            // tile row in po
        int tc = (t & 7) * 32;             // tile col in po
        __shared__ float s_t[32][33];
        int x = tid & 31, y = tid >> 5;    // (col, row) in tile, 8 rows/iter
        #pragma unroll
        for (int i = 0; i < 4; i++)
            s_t[y + i * 8][x] = po[(tr + y + i * 8) * 256 + tc + x];
        __syncthreads();
        #pragma unroll
        for (int i = 0; i < 4; i++)
            g_poT[(tc + y + i * 8) * 256 + tr + x] = s_t[x][y + i * 8];
    }
}

// ---------------------------------------------------------------------------
// k_compat: one block per (h,b,v) = 512 blocks, 256 threads (8 warps).
// QUAD layout: 4 lanes per n (each covers 8 of the 32 k's via 2 float4 loads),
// depth-2 shfl_xor closes the dot. 8 n per warp-iteration, 16 iterations.
// compat[n] -> smem + global; block-reduce rowmax + local sumexp -> g_ms2.
// ---------------------------------------------------------------------------
__global__ __launch_bounds__(256) void k_compat(
    const float* __restrict__ ndf,   // (B,V,N,8)
    const float* __restrict__ gKs)   // (H,B,1,N,32)
{
    __shared__ __align__(16) float s_c[Nc];
    __shared__ __align__(16) float s_red[256];
    __shared__ __align__(16) float s_wk[8];
    __shared__ __align__(16) float qsm[32];

    int hbv = blockIdx.x;
    int h = hbv >> 6, bv = hbv & 63;
    int b = bv >> 3;
    int tid = threadIdx.x, warp = tid >> 5, lane = tid & 31;

    // warp 0: stash q slice, compute wk = M_K^T q (butterfly, all lanes in shfl)
    if (warp == 0) {
        float qv = g_q[bv * 256 + h * 32 + lane];
        qsm[lane] = qv;
        const float* mr = g_M + (256 + h * 32 + lane) * 8;
        float p[8];
        #pragma unroll
        for (int f = 0; f < 8; f++) p[f] = qv * mr[f];
        #pragma unroll
        for (int f = 0; f < 8; f++) {
            #pragma unroll
            for (int o = 16; o > 0; o >>= 1)
                p[f] += __shfl_xor_sync(0xffffffffu, p[f], o);
        }
        if (lane == 0) {
            #pragma unroll
            for (int f = 0; f < 8; f++) s_wk[f] = p[f];
        }
    }
    __syncthreads();

    float wk[8];
    #pragma unroll
    for (int f = 0; f < 8; f++) wk[f] = s_wk[f];

    int q = lane & 3;
    float4 qa = ((const float4*)qsm)[q * 2];
    float4 qb = ((const float4*)qsm)[q * 2 + 1];

    const float inv_sqrt_ks = 0.17677669529663688f;   // 1/sqrt(32)
    const float4* fbase = (const float4*)(ndf + bv * Nc * 8);
    const float* gk = gKs + (h * Bc + b) * Nc * 32;
    const unsigned char* mrow = g_mask + bv * Nc;
    float* gcomp = g_compat + hbv * Nc;

    #pragma unroll 4
    for (int it = 0; it < 16; it++) {
        int n = it * 64 + warp * 8 + (lane >> 2);
        int nl = (n < Nc) ? n : (Nc - 1);
        const float* gr = gk + nl * 32 + q * 8;
        float4 ga = *(const float4*)gr;
        float4 gb = *(const float4*)(gr + 4);
        float p = qa.x*ga.x + qa.y*ga.y + qa.z*ga.z + qa.w*ga.w
                + qb.x*gb.x + qb.y*gb.y + qb.z*gb.z + qb.w*gb.w;
        p += __shfl_xor_sync(0xffffffffu, p, 1);
        p += __shfl_xor_sync(0xffffffffu, p, 2);
        float4 f0 = fbase[nl * 2];
        float4 f1 = fbase[nl * 2 + 1];
        p += wk[0]*f0.x + wk[1]*f0.y + wk[2]*f0.z + wk[3]*f0.w
           + wk[4]*f1.x + wk[5]*f1.y + wk[6]*f1.z + wk[7]*f1.w;
        float c = p * inv_sqrt_ks;
        if (!mrow[nl]) c = NEG_INF;
        if (q == 0 && n < Nc) { s_c[n] = c; gcomp[n] = c; }
    }
    __syncthreads();

    // row max
    float m = NEG_INF;
    for (int i = tid; i < Nc; i += 256) m = fmaxf(m, s_c[i]);
    s_red[tid] = m;
    __syncthreads();
    for (int s = 128; s > 0; s >>= 1) {
        if (tid < s) s_red[tid] = fmaxf(s_red[tid], s_red[tid + s]);
        __syncthreads();
    }
    m = s_red[0];
    __syncthreads();

    // local sumexp
    float ss = 0.f;
    for (int i = tid; i < Nc; i += 256) ss += expf(s_c[i] - m);
    s_red[tid] = ss;
    __syncthreads();
    for (int s = 128; s > 0; s >>= 1) {
        if (tid < s) s_red[tid] += s_red[tid + s];
        __syncthreads();
    }
    if (tid == 0) { g_ms2[hbv * 2] = m; g_ms2[hbv * 2 + 1] = s_red[0]; }
}

// ---------------------------------------------------------------------------
// k_heads: one block per (h,b,v) = 512 blocks, 256 threads. QUAD layout.
// Joint (h,b) normalizer from 8 per-v partials, then
// heads[h,b,v,k] = sum_n attn*gV_s[n,k] + M_V[k]·(sum_n attn*ndf8[n]).
// ---------------------------------------------------------------------------
__global__ __launch_bounds__(256) void k_heads(
    const float* __restrict__ ndf,   // (B,V,N,8)
    const float* __restrict__ gVs)   // (H,B,1,N,32)
{
    __shared__ __align__(16) float s_c[Nc];
    __shared__ __align__(16) float s_acc[8 * 32];
    __shared__ __align__(16) float s_sf[8 * 8];
    __shared__ __align__(16) float s_MS[4];

    int hbv = blockIdx.x;
    int h = hbv >> 6, bv = hbv & 63;
    int b = bv >> 3;
    int tid = threadIdx.x, warp = tid >> 5, lane = tid & 31;

    // joint (h,b) normalizer (warp 0; all 32 lanes participate in shfls)
    if (warp == 0) {
        float m = NEG_INF, s = 0.f;
        if (lane < 8) {
            int idx = (h * 64 + b * 8 + lane) * 2;
            m = g_ms2[idx];
            s = g_ms2[idx + 1];
        }
        float M = m;
        #pragma unroll
        for (int o = 4; o > 0; o >>= 1) M = fmaxf(M, __shfl_xor_sync(0xffffffffu, M, o));
        float se = (lane < 8) ? s * expf(m - M) : 0.f;
        #pragma unroll
        for (int o = 4; o > 0; o >>= 1) se += __shfl_xor_sync(0xffffffffu, se, o);
        if (lane == 0) { s_MS[0] = M; s_MS[1] = 1.0f / se; }
    }
    const float* gcomp = g_compat + hbv * Nc;
    for (int i = tid; i < Nc; i += 256) s_c[i] = gcomp[i];
    __syncthreads();

    float M = s_MS[0], invS = s_MS[1];

    const float4* fbase = (const float4*)(ndf + bv * Nc * 8);
    const float* gv = gVs + (h * Bc + b) * Nc * 32;

    int q = lane & 3;
    float4 aca = make_float4(0.f,0.f,0.f,0.f);
    float4 acb = make_float4(0.f,0.f,0.f,0.f);
    float sf[8] = {0.f,0.f,0.f,0.f,0.f,0.f,0.f,0.f};

    #pragma unroll 4
    for (int it = 0; it < 16; it++) {
        int n = it * 64 + warp * 8 + (lane >> 2);
        int nl = (n < Nc) ? n : (Nc - 1);
        float w = (n < Nc) ? expf(s_c[nl] - M) * invS : 0.f;
        const float* gr = gv + nl * 32 + q * 8;
        float4 ga = *(const float4*)gr;
        float4 gb = *(const float4*)(gr + 4);
        aca.x += w * ga.x; aca.y += w * ga.y; aca.z += w * ga.z; aca.w += w * ga.w;
        acb.x += w * gb.x; acb.y += w * gb.y; acb.z += w * gb.z; acb.w += w * gb.w;
        float4 f0 = fbase[nl * 2];
        float4 f1 = fbase[nl * 2 + 1];
        sf[0] += w * f0.x; sf[1] += w * f0.y; sf[2] += w * f0.z; sf[3] += w * f0.w;
        sf[4] += w * f1.x; sf[5] += w * f1.y; sf[6] += w * f1.z; sf[7] += w * f1.w;
    }
    // reduce across quad-columns (lanes sharing q): offsets 4, 8, 16
    #pragma unroll
    for (int o = 4; o <= 16; o <<= 1) {
        aca.x += __shfl_xor_sync(0xffffffffu, aca.x, o);
        aca.y += __shfl_xor_sync(0xffffffffu, aca.y, o);
        aca.z += __shfl_xor_sync(0xffffffffu, aca.z, o);
        aca.w += __shfl_xor_sync(0xffffffffu, aca.w, o);
        acb.x += __shfl_xor_sync(0xffffffffu, acb.x, o);
        acb.y += __shfl_xor_sync(0xffffffffu, acb.y, o);
        acb.z += __shfl_xor_sync(0xffffffffu, acb.z, o);
        acb.w += __shfl_xor_sync(0xffffffffu, acb.w, o);
        #pragma unroll
        for (int f = 0; f < 8; f++) sf[f] += __shfl_xor_sync(0xffffffffu, sf[f], o);
    }
    if (lane < 4) {
        ((float4*)(s_acc + warp * 32 + lane * 8))[0] = aca;
        ((float4*)(s_acc + warp * 32 + lane * 8))[1] = acb;
    }
    if (lane == 0) {
        #pragma unroll
        for (int f = 0; f < 8; f++) s_sf[warp * 8 + f] = sf[f];
    }
    __syncthreads();

    if (warp == 0) {
        float a = 0.f;
        #pragma unroll
        for (int w = 0; w < 8; w++) a += s_acc[w * 32 + lane];
        float sft[8];
        #pragma unroll
        for (int f = 0; f < 8; f++) {
            float t = 0.f;
            #pragma unroll
            for (int w = 0; w < 8; w++) t += s_sf[w * 8 + f];
            sft[f] = t;
        }
        const float* cvrow = g_M + (h * 32 + lane) * 8;   // gV-dyn coeffs
        float dyn = cvrow[0]*sft[0] + cvrow[1]*sft[1] + cvrow[2]*sft[2] + cvrow[3]*sft[3]
                  + cvrow[4]*sft[4] + cvrow[5]*sft[5] + cvrow[6]*sft[6] + cvrow[7]*sft[7];
        g_heads[bv * 256 + h * 32 + lane] = a + dyn;
    }
}

// ---------------------------------------------------------------------------
// k_fq: fq[bv][d] = sum_j poT[j][d] * heads[bv][j]  — thread-per-d, fully
// coalesced (warp covers one 128B line per j), zero shuffles, pure FMA stream.
// Then wl = M_L^T @ fq via per-warp reductions.
// ---------------------------------------------------------------------------
__global__ __launch_bounds__(256) void k_fq()
{
    int bv = blockIdx.x;
    int tid = threadIdx.x, warp = tid >> 5, lane = tid & 31;
    __shared__ __align__(16) float hsm[256];
    __shared__ __align__(16) float fqsm[256];
    hsm[tid] = g_heads[bv * 256 + tid];
    __syncthreads();

    float acc = 0.f;
    const float* pt = g_poT + tid;
    #pragma unroll 16
    for (int j = 0; j < 256; j++) acc += pt[j * 256] * hsm[j];

    g_fq[bv * 256 + tid] = acc;
    fqsm[tid] = acc;
    __syncthreads();

    // wl[f] = sum_d fq[d] * M_L[d][f] ; warp w handles f = w
    float a = 0.f;
    for (int d = lane; d < 256; d += 32) a += fqsm[d] * g_M[(512 + d) * 8 + warp];
    #pragma unroll
    for (int o = 16; o > 0; o >>= 1) a += __shfl_xor_sync(0xffffffffu, a, o);
    if (lane == 0) g_wl[bv * 8 + warp] = a;
}

// ---------------------------------------------------------------------------
// k_logits: logits[b,v,n] = tanh((dot256(fq, lK_s[n]) + dot8(wl, ndf8))/16)*10,
// masked. grid (64 bv, 8 tiles of 125 n), 256 thr, warp-per-n, float4 loads.
// ---------------------------------------------------------------------------
__global__ __launch_bounds__(256) void k_logits(
    const float* __restrict__ ndf,             // (B,V,N,8)
    const float* __restrict__ lKs)             // (B,1,N,256)
{
    int bv = blockIdx.x;
    int b = bv >> 3;
    int tile = blockIdx.y;                     // 0..7
    int tid = threadIdx.x, warp = tid >> 5, lane = tid & 31;

    __shared__ __align__(16) float fqsm[256];
    __shared__ __align__(16) float wlsm[8];
    fqsm[tid] = g_fq[bv * 256 + tid];
    if (tid < 8) wlsm[tid] = g_wl[bv * 8 + tid];
    __syncthreads();

    float4 fqa = ((const float4*)fqsm)[lane * 2];
    float4 fqb = ((const float4*)fqsm)[lane * 2 + 1];
    float wl[8];
    #pragma unroll
    for (int f = 0; f < 8; f++) wl[f] = wlsm[f];

    const float4* fbase = (const float4*)(ndf + bv * Nc * 8);
    const float* lk = lKs + b * Nc * 256;
    const unsigned char* mrow = g_mask + bv * Nc;

    int n0 = tile * 125;
    for (int n = n0 + warp; n < n0 + 125; n += 8) {
        const float* lkr = lk + n * 256 + lane * 8;
        float4 v0 = *(const float4*)lkr;
        float4 v1 = *(const float4*)(lkr + 4);
        float4 f0 = fbase[n * 2];
        float4 f1 = fbase[n * 2 + 1];
        float p = fqa.x*v0.x + fqa.y*v0.y + fqa.z*v0.z + fqa.w*v0.w
                + fqb.x*v1.x + fqb.y*v1.y + fqb.z*v1.z + fqb.w*v1.w;
        #pragma unroll
        for (int o = 16; o > 0; o >>= 1) p += __shfl_xor_sync(0xffffffffu, p, o);
        if (lane == 0) {
            p += wl[0]*f0.x + wl[1]*f0.y + wl[2]*f0.z + wl[3]*f0.w
               + wl[4]*f1.x + wl[5]*f1.y + wl[6]*f1.z + wl[7]*f1.w;
            float lg = tanhf(p * 0.0625f) * 10.0f;
            if (!mrow[n]) lg = NEG_INF;
            g_logits[bv * Nc + n] = lg;
        }
    }
}

// ---------------------------------------------------------------------------
// k_sel: ONE block, 1024 threads = 8 groups of 128 (one per batch b).
// Per-b: argmax (first-index tie-break) + sumexp -> vec/node/logprob;
// then in-block entropy combine. Writes all 25 outputs.
// ---------------------------------------------------------------------------
__global__ __launch_bounds__(1024) void k_sel(float* __restrict__ out)
{
    __shared__ __align__(16) float s_v[32];
    __shared__ __align__(16) int   s_i[32];
    __shared__ __align__(16) float s_m[8];
    __shared__ __align__(16) float s_s[32];
    __shared__ __align__(16) float s_e[8];

    int tid = threadIdx.x;
    int g = tid >> 7, t = tid & 127;           // group = batch, 4 warps per group
    int wig = t >> 5, lane = tid & 31;
    const float* lg = g_logits + g * 8000;

    // local argmax (ascending stride keeps first occurrence)
    float bm = NEG_INF; int bi = 0x7fffffff;
    for (int i = t; i < 8000; i += 128) {
        float x = lg[i];
        if (x > bm) { bm = x; bi = i; }
    }
    // warp reduce (val, idx), smaller idx wins ties
    #pragma unroll
    for (int o = 16; o > 0; o >>= 1) {
        float xv = __shfl_down_sync(0xffffffffu, bm, o);
        int   xi = __shfl_down_sync(0xffffffffu, bi, o);
        if (xv > bm || (xv == bm && xi < bi)) { bm = xv; bi = xi; }
    }
    if (lane == 0) { s_v[g * 4 + wig] = bm; s_i[g * 4 + wig] = bi; }
    __syncthreads();

    int op = 0;
    if (t == 0) {
        float m = s_v[g * 4]; op = s_i[g * 4];
        #pragma unroll
        for (int w = 1; w < 4; w++) {
            float xv = s_v[g * 4 + w]; int xi = s_i[g * 4 + w];
            if (xv > m || (xv == m && xi < op)) { m = xv; op = xi; }
        }
        s_m[g] = m;
    }
    __syncthreads();

    float m = s_m[g];
    float ssum = 0.f;
    for (int i = t; i < 8000; i += 128) ssum += expf(lg[i] - m);
    #pragma unroll
    for (int o = 16; o > 0; o >>= 1) ssum += __shfl_xor_sync(0xffffffffu, ssum, o);
    if (lane == 0) s_s[g * 4 + wig] = ssum;
    __syncthreads();

    if (t == 0) {
        float total = s_s[g * 4] + s_s[g * 4 + 1] + s_s[g * 4 + 2] + s_s[g * 4 + 3];
        float prob    = 1.0f / total;
        float logprob = -logf(total);
        out[g]      = (float)(op / Nc);
        out[8 + g]  = (float)(op % Nc);
        out[16 + g] = logprob;
        s_e[g]      = prob * logprob;
    }
    __syncthreads();
    if (tid == 0) {
        float e = 0.f;
        #pragma unroll
        for (int b = 0; b < 8; b++) e += s_e[b];
        out[24] = -e;
    }
}

// ---------------------------------------------------------------------------
extern "C" void kernel_launch(void* const* d_in, const int* in_sizes, int n_in,
                              void* d_out, int out_size)
{
    const float* fc   = (const float*)d_in[1];   // fixed_context
    const float* prev = (const float*)d_in[2];   // prev_node_embeddings
    const float* ndf  = (const float*)d_in[3];   // node_dynamic_features
    const float* veh  = (const float*)d_in[4];   // vehicle_dynamic_features
    const float* gVs  = (const float*)d_in[5];   // glimpse_V_static
    const float* gKs  = (const float*)d_in[6];   // glimpse_K_static
    const float* lKs  = (const float*)d_in[7];   // logit_K_static
    const void*  mask = (const void*)d_in[8];    // feasibility_mask (dtype auto-detected)
    const float* pcs  = (const float*)d_in[9];
    const float* pns1 = (const float*)d_in[10];
    const float* pns2 = (const float*)d_in[11];
    const float* po   = (const float*)d_in[12];
    float* out = (float*)d_out;

    k_pre<<<288, 256>>>(pns1, pns2, prev, veh, fc, pcs, po, mask);
    k_compat<<<512, 256>>>(ndf, gKs);
    k_heads<<<512, 256>>>(ndf, gVs);
    k_fq<<<64, 256>>>();
    dim3 gl(64, 8);
    k_logits<<<gl, 256>>>(ndf, lKs);
    k_sel<<<1, 1024>>>(out);
}